// round 14
// baseline (speedup 1.0000x reference)
#include <cuda_runtime.h>
#include <cuda_bf16.h>
#include <cstdint>
#include <cstddef>

// Problem constants
#define BB 2
#define SS 2048
#define HH 4096
#define NH 32
#define HD 128
#define NTOK (BB * SS)   // 4096
#define NSPLIT 8

// ---------------------------------------------------------------------------
// Scratch (allocation-free: __device__ globals)
// ---------------------------------------------------------------------------
__device__ float g_Q[NTOK * HH];            // 64 MB
__device__ float g_K[NTOK * HD];            // 2 MB
__device__ float g_V[NTOK * HD];            // 2 MB
__device__ float g_O[NTOK * HH];            // 64 MB (attention out, tf32-rounded)
__device__ float g_KP[NSPLIT * NTOK * HD];  // split-K partials
__device__ float g_VP[NSPLIT * NTOK * HD];
__device__ float g_HSR[NTOK * HH];          // tf32-rounded hidden states
__device__ float g_WQR[HH * HH];            // tf32-rounded Wq
__device__ float g_WDR[HH * HH];            // tf32-rounded Wd

__device__ __forceinline__ uint32_t f2tf32(float x) {
    uint32_t y;
    asm("cvt.rna.tf32.f32 %0, %1;" : "=r"(y) : "f"(x));
    return y;
}
__device__ __forceinline__ float rtf32(float x) {
    return __uint_as_float(f2tf32(x));
}
__device__ __forceinline__ float ex2f(float x) {
    float y;
    asm("ex2.approx.ftz.f32 %0, %1;" : "=f"(y) : "f"(x));
    return y;
}
__device__ __forceinline__ uint32_t smem_u32(const void* p) {
    uint32_t a;
    asm("{ .reg .u64 t; cvta.to.shared.u64 t, %1; cvt.u32.u64 %0, t; }" : "=r"(a) : "l"(p));
    return a;
}
__device__ __forceinline__ void cp16(uint32_t dst, const void* src) {
    asm volatile("cp.async.cg.shared.global [%0], [%1], 16;" :: "r"(dst), "l"(src) : "memory");
}
__device__ __forceinline__ void cp_commit() {
    asm volatile("cp.async.commit_group;" ::: "memory");
}
__device__ __forceinline__ void mma8(float* d, const uint32_t* a, uint32_t b0, uint32_t b1) {
    asm volatile(
        "mma.sync.aligned.m16n8k8.row.col.f32.tf32.tf32.f32 "
        "{%0,%1,%2,%3}, {%4,%5,%6,%7}, {%8,%9}, {%0,%1,%2,%3};"
        : "+f"(d[0]), "+f"(d[1]), "+f"(d[2]), "+f"(d[3])
        : "r"(a[0]), "r"(a[1]), "r"(a[2]), "r"(a[3]), "r"(b0), "r"(b1));
}

// ---------------------------------------------------------------------------
// tf32 pre-round: out[i] = rtf32(in[i])
// ---------------------------------------------------------------------------
__global__ __launch_bounds__(256)
void round_tf32(const float* __restrict__ in, float* __restrict__ out, int n)
{
    int i = (blockIdx.x * blockDim.x + threadIdx.x) * 4;
    if (i >= n) return;
    float4 v = *(const float4*)(in + i);
    *(float4*)(out + i) = make_float4(rtf32(v.x), rtf32(v.y), rtf32(v.z), rtf32(v.w));
}

// ---------------------------------------------------------------------------
// Big GEMM (NT), inputs PRE-ROUNDED to tf32: C[m,n] = sum_k A[m,k]*W[n,k]
// BM=128, BN=256, BK=32, 256 threads, 8 warps (2x4), warp tile 64x64.
// 3-stage cp.async pipeline. M=N=K=4096.
// ---------------------------------------------------------------------------
#define NBK 32
#define NTSTR 36
#define BIG_STG ((128 + 256) * NTSTR)          // floats per stage (13824)
#define BIG_SMEM (3 * BIG_STG * 4)             // 165888 B

__global__ __launch_bounds__(256)
void gemm_big(const float* __restrict__ A, const float* __restrict__ W,
              float* __restrict__ C)
{
    constexpr int K = HH, N = HH;
    extern __shared__ float smem[];

    const int tid = threadIdx.x;
    const int lane = tid & 31, wid = tid >> 5;
    const int wm = wid & 1, wn = wid >> 1;           // 2 x 4 warps
    const int m0 = blockIdx.y * 128, n0 = blockIdx.x * 256;
    const uint32_t sb = smem_u32(smem);

    const float* Ag0 = A + (size_t)m0 * K;
    const float* Wg0 = W + (size_t)n0 * K;

    float d[4][8][4];
#pragma unroll
    for (int i = 0; i < 4; i++)
#pragma unroll
        for (int j = 0; j < 8; j++)
#pragma unroll
            for (int q = 0; q < 4; q++) d[i][j][q] = 0.f;

    const int nch = K / NBK;   // 128
    const int lrA = tid >> 3, lsg = (tid & 7) << 2;

    auto issue = [&](int c) {
        const int s = c % 3;
        const uint32_t dA = sb + (uint32_t)(s * BIG_STG) * 4;
        const uint32_t dB = dA + 128 * NTSTR * 4;
        const float* Ag = Ag0 + c * NBK;
        const float* Wg = Wg0 + c * NBK;
#pragma unroll
        for (int u = 0; u < 4; u++) {
            int r = lrA + u * 32;
            cp16(dA + (uint32_t)(r * NTSTR + lsg) * 4, Ag + (size_t)r * K + lsg);
        }
#pragma unroll
        for (int u = 0; u < 8; u++) {
            int r = lrA + u * 32;
            cp16(dB + (uint32_t)(r * NTSTR + lsg) * 4, Wg + (size_t)r * K + lsg);
        }
        cp_commit();
    };

    issue(0);
    issue(1);

    for (int c = 0; c < nch; c++) {
        if (c == nch - 1) {
            asm volatile("cp.async.wait_group 0;" ::: "memory");
        } else {
            asm volatile("cp.async.wait_group 1;" ::: "memory");
        }
        __syncthreads();
        if (c + 2 < nch) issue(c + 2);

        const float* as = smem + (c % 3) * BIG_STG;
        const float* bs = as + 128 * NTSTR;
#pragma unroll
        for (int ks = 0; ks < 4; ks++) {
            const int kb = ks * 8 + (lane & 3);
            uint32_t af[4][4];
#pragma unroll
            for (int i = 0; i < 4; i++) {
                int r = wm * 64 + i * 16 + (lane >> 2);
                af[i][0] = *(const uint32_t*)&as[r * NTSTR + kb];
                af[i][1] = *(const uint32_t*)&as[(r + 8) * NTSTR + kb];
                af[i][2] = *(const uint32_t*)&as[r * NTSTR + kb + 4];
                af[i][3] = *(const uint32_t*)&as[(r + 8) * NTSTR + kb + 4];
            }
#pragma unroll
            for (int j = 0; j < 8; j++) {
                int n = wn * 64 + j * 8 + (lane >> 2);
                uint32_t b0 = *(const uint32_t*)&bs[n * NTSTR + kb];
                uint32_t b1 = *(const uint32_t*)&bs[n * NTSTR + kb + 4];
#pragma unroll
                for (int i = 0; i < 4; i++)
                    mma8(d[i][j], af[i], b0, b1);
            }
        }
        __syncthreads();
    }

#pragma unroll
    for (int i = 0; i < 4; i++) {
        int r0 = m0 + wm * 64 + i * 16 + (lane >> 2);
#pragma unroll
        for (int j = 0; j < 8; j++) {
            int cc = n0 + wn * 64 + j * 8 + (lane & 3) * 2;
            *(float2*)(C + (size_t)r0 * N + cc)       = make_float2(d[i][j][0], d[i][j][1]);
            *(float2*)(C + (size_t)(r0 + 8) * N + cc) = make_float2(d[i][j][2], d[i][j][3]);
        }
    }
}

// ---------------------------------------------------------------------------
// Small GEMM (NT) with split-K (for K/V projections), rounds inputs itself.
// ---------------------------------------------------------------------------
#define GBK 32
#define TSTR 36

__global__ __launch_bounds__(256)
void gemm_mma(const float* __restrict__ A, const float* __restrict__ W,
              float* __restrict__ C, int M, int N, int K, int kspl)
{
    extern __shared__ float smem[];
    float* As[2] = { smem,                  smem + 128 * TSTR };
    float* Bs[2] = { smem + 2 * 128 * TSTR, smem + 3 * 128 * TSTR };

    const int tid = threadIdx.x;
    const int lane = tid & 31, wid = tid >> 5;
    const int wm = wid & 1, wn = wid >> 1;
    const int m0 = blockIdx.y * 128, n0 = blockIdx.x * 128;
    const int z = blockIdx.z;

    const int lr = tid >> 3;
    const int lc = (tid & 7) << 2;

    const float* Ag = A + (size_t)m0 * K + (size_t)z * kspl;
    const float* Wg = W + (size_t)n0 * K + (size_t)z * kspl;
    C += (size_t)z * M * N;

    float d[4][4][4];
#pragma unroll
    for (int i = 0; i < 4; i++)
#pragma unroll
        for (int j = 0; j < 4; j++)
#pragma unroll
            for (int q = 0; q < 4; q++) d[i][j][q] = 0.f;

    const int nch = kspl / GBK;
    float4 pa[4], pb[4];

#pragma unroll
    for (int u = 0; u < 4; u++) {
        int r = lr + u * 32;
        pa[u] = *(const float4*)(Ag + (size_t)r * K + lc);
        pb[u] = *(const float4*)(Wg + (size_t)r * K + lc);
    }
#pragma unroll
    for (int u = 0; u < 4; u++) {
        int r = lr + u * 32;
        *(float4*)(As[0] + r * TSTR + lc) =
            make_float4(rtf32(pa[u].x), rtf32(pa[u].y), rtf32(pa[u].z), rtf32(pa[u].w));
        *(float4*)(Bs[0] + r * TSTR + lc) =
            make_float4(rtf32(pb[u].x), rtf32(pb[u].y), rtf32(pb[u].z), rtf32(pb[u].w));
    }
    __syncthreads();

    for (int c = 0; c < nch; c++) {
        const int s = c & 1;

        if (c + 1 < nch) {
            const float* Agn = Ag + (c + 1) * GBK;
            const float* Wgn = Wg + (c + 1) * GBK;
#pragma unroll
            for (int u = 0; u < 4; u++) {
                int r = lr + u * 32;
                pa[u] = *(const float4*)(Agn + (size_t)r * K + lc);
                pb[u] = *(const float4*)(Wgn + (size_t)r * K + lc);
            }
        }

        const float* as = As[s];
        const float* bs = Bs[s];
#pragma unroll
        for (int ks = 0; ks < 4; ks++) {
            const int kb = ks * 8 + (lane & 3);
            uint32_t af[4][4];
#pragma unroll
            for (int i = 0; i < 4; i++) {
                int r = wm * 64 + i * 16 + (lane >> 2);
                af[i][0] = *(const uint32_t*)&as[r * TSTR + kb];
                af[i][1] = *(const uint32_t*)&as[(r + 8) * TSTR + kb];
                af[i][2] = *(const uint32_t*)&as[r * TSTR + kb + 4];
                af[i][3] = *(const uint32_t*)&as[(r + 8) * TSTR + kb + 4];
            }
            uint32_t bf[4][2];
#pragma unroll
            for (int j = 0; j < 4; j++) {
                int n = wn * 32 + j * 8 + (lane >> 2);
                bf[j][0] = *(const uint32_t*)&bs[n * TSTR + kb];
                bf[j][1] = *(const uint32_t*)&bs[n * TSTR + kb + 4];
            }
#pragma unroll
            for (int i = 0; i < 4; i++)
#pragma unroll
                for (int j = 0; j < 4; j++)
                    mma8(d[i][j], af[i], bf[j][0], bf[j][1]);
        }

        if (c + 1 < nch) {
            const int s2 = s ^ 1;
#pragma unroll
            for (int u = 0; u < 4; u++) {
                int r = lr + u * 32;
                *(float4*)(As[s2] + r * TSTR + lc) =
                    make_float4(rtf32(pa[u].x), rtf32(pa[u].y), rtf32(pa[u].z), rtf32(pa[u].w));
                *(float4*)(Bs[s2] + r * TSTR + lc) =
                    make_float4(rtf32(pb[u].x), rtf32(pb[u].y), rtf32(pb[u].z), rtf32(pb[u].w));
            }
        }
        __syncthreads();
    }

#pragma unroll
    for (int i = 0; i < 4; i++) {
        int r0 = m0 + wm * 64 + i * 16 + (lane >> 2);
#pragma unroll
        for (int j = 0; j < 4; j++) {
            int cc = n0 + wn * 32 + j * 8 + (lane & 3) * 2;
            *(float2*)(C + (size_t)r0 * N + cc)       = make_float2(d[i][j][0], d[i][j][1]);
            *(float2*)(C + (size_t)(r0 + 8) * N + cc) = make_float2(d[i][j][2], d[i][j][3]);
        }
    }
}

// ---------------------------------------------------------------------------
// Split-K reduction
// ---------------------------------------------------------------------------
__global__ __launch_bounds__(256)
void reduce_split(const float* __restrict__ part, float* __restrict__ out,
                  int n, int rnd)
{
    int i = (blockIdx.x * blockDim.x + threadIdx.x) * 4;
    if (i >= n) return;
    float4 acc = *(const float4*)(part + i);
#pragma unroll
    for (int s = 1; s < NSPLIT; s++) {
        float4 v = *(const float4*)(part + (size_t)s * n + i);
        acc.x += v.x; acc.y += v.y; acc.z += v.z; acc.w += v.w;
    }
    if (rnd) {
        acc.x = rtf32(acc.x); acc.y = rtf32(acc.y);
        acc.z = rtf32(acc.z); acc.w = rtf32(acc.w);
    }
    *(float4*)(out + i) = acc;
}

// ---------------------------------------------------------------------------
// RoPE
// ---------------------------------------------------------------------------
#define QSC (0.08838834764831845f * 1.4426950408889634f)

__global__ __launch_bounds__(256) void rope_q_kernel(
    float* __restrict__ Q, const float* __restrict__ cosp, const float* __restrict__ sinp)
{
    int i = blockIdx.x * blockDim.x + threadIdx.x;
    if (i >= NTOK * NH * 64) return;
    int d = i & 63;
    int h = (i >> 6) & 31;
    int t = i >> 11;
    int s = t & (SS - 1);
    float* q = Q + (size_t)t * HH + h * HD;
    float c1 = cosp[s * HD + d],      s1 = sinp[s * HD + d];
    float c2 = cosp[s * HD + d + 64], s2 = sinp[s * HD + d + 64];
    float x1 = q[d], x2 = q[d + 64];
    q[d]      = rtf32((x1 * c1 - x2 * s1) * QSC);
    q[d + 64] = rtf32((x2 * c2 + x1 * s2) * QSC);
}

__global__ __launch_bounds__(256) void rope_k_kernel(
    float* __restrict__ K, const float* __restrict__ cosp, const float* __restrict__ sinp)
{
    int i = blockIdx.x * blockDim.x + threadIdx.x;
    if (i >= NTOK * 64) return;
    int d = i & 63;
    int t = i >> 6;
    int s = t & (SS - 1);
    float* k = K + (size_t)t * HD;
    float c1 = cosp[s * HD + d],      s1 = sinp[s * HD + d];
    float c2 = cosp[s * HD + d + 64], s2 = sinp[s * HD + d + 64];
    float x1 = k[d], x2 = k[d + 64];
    k[d]      = rtf32(x1 * c1 - x2 * s1);
    k[d + 64] = rtf32(x2 * c2 + x1 * s2);
}

// ---------------------------------------------------------------------------
// Tensor-core flash attention (TF32 mma.sync), causal, MQA.
// O written tf32-rounded (Wd's cp.async path needs pre-rounded input).
// ---------------------------------------------------------------------------
#define ABQ 128
#define ABKV 64
#define KV_STR 136
#define P_STR 68
#define BUF_FLOATS 17408
#define P_OFF (2 * BUF_FLOATS)
#define ATT_SMEM_FLOATS (P_OFF + 128 * P_STR)
#define NEGINF (-1e30f)

__global__ __launch_bounds__(256)
void attn_mma(const float* __restrict__ Q, const float* __restrict__ Kg,
              const float* __restrict__ Vg, float* __restrict__ O)
{
    extern __shared__ float sm[];
    const int tid = threadIdx.x;
    const int lane = tid & 31, w = tid >> 5;
    const int qb = (int)gridDim.x - 1 - (int)blockIdx.x;
    const int h = blockIdx.y, b = blockIdx.z;
    const int q0 = qb * ABQ;
    const uint32_t sb = smem_u32(sm);

    {
        const float* Qg = Q + ((size_t)(b * SS + q0)) * HH + h * HD;
#pragma unroll
        for (int j = 0; j < 16; j++) {
            int i = tid + j * 256;
            int r = i >> 5, c = (i & 31) * 4;
            *(float4*)&sm[r * KV_STR + c] = *(const float4*)(Qg + (size_t)r * HH + c);
        }
    }
    __syncthreads();

    uint32_t qf[16][4];
    {
        const int r = 16 * w + (lane >> 2);
#pragma unroll
        for (int ks = 0; ks < 16; ks++) {
            int base = r * KV_STR + 8 * ks + (lane & 3);
            qf[ks][0] = *(const uint32_t*)&sm[base];
            qf[ks][1] = *(const uint32_t*)&sm[base + 8 * KV_STR];
            qf[ks][2] = *(const uint32_t*)&sm[base + 4];
            qf[ks][3] = *(const uint32_t*)&sm[base + 8 * KV_STR + 4];
        }
    }
    __syncthreads();

    float oacc[16][4];
#pragma unroll
    for (int n = 0; n < 16; n++)
#pragma unroll
        for (int q = 0; q < 4; q++) oacc[n][q] = 0.f;

    float m1 = NEGINF, m2 = NEGINF, l1 = 0.f, l2 = 0.f;

    const int ntile = (q0 + ABQ) / ABKV;
    const float* Kbase = Kg + (size_t)(b * SS) * HD;
    const float* Vbase = Vg + (size_t)(b * SS) * HD;
    const int qlo = q0 + 16 * w;
    const int qrow = qlo + (lane >> 2);

    {
#pragma unroll
        for (int j = 0; j < 8; j++) {
            int r = 8 * w + j;
            cp16(sb + (r * KV_STR + lane * 4) * 4, Kbase + (size_t)r * HD + lane * 4);
            cp16(sb + (8704 + r * KV_STR + lane * 4) * 4, Vbase + (size_t)r * HD + lane * 4);
        }
        cp_commit();
    }

    for (int t = 0; t < ntile; t++) {
        const int k0 = t * ABKV;

        if (t + 1 < ntile) {
            const int bufo = ((t + 1) & 1) * BUF_FLOATS;
            const float* Ks = Kbase + (size_t)(k0 + ABKV) * HD;
            const float* Vs = Vbase + (size_t)(k0 + ABKV) * HD;
#pragma unroll
            for (int j = 0; j < 8; j++) {
                int r = 8 * w + j;
                cp16(sb + (bufo + r * KV_STR + lane * 4) * 4, Ks + (size_t)r * HD + lane * 4);
                cp16(sb + (bufo + 8704 + r * KV_STR + lane * 4) * 4, Vs + (size_t)r * HD + lane * 4);
            }
            cp_commit();
            asm volatile("cp.async.wait_group 1;" ::: "memory");
        } else {
            asm volatile("cp.async.wait_group 0;" ::: "memory");
        }
        __syncthreads();

        if (k0 <= qlo + 15) {
            const float* Kb = sm + (t & 1) * BUF_FLOATS;
            const float* Vb = Kb + 8704;
            float* Pw = sm + P_OFF;

            float sacc[8][4];
#pragma unroll
            for (int n = 0; n < 8; n++)
#pragma unroll
                for (int q = 0; q < 4; q++) sacc[n][q] = 0.f;

#pragma unroll
            for (int ks = 0; ks < 16; ks++) {
                uint32_t bf[8][2];
#pragma unroll
                for (int nf = 0; nf < 8; nf++) {
                    int a = (8 * nf + (lane >> 2)) * KV_STR + 8 * ks + (lane & 3);
                    bf[nf][0] = *(const uint32_t*)&Kb[a];
                    bf[nf][1] = *(const uint32_t*)&Kb[a + 4];
                }
#pragma unroll
                for (int nf = 0; nf < 8; nf++)
                    mma8(sacc[nf], qf[ks], bf[nf][0], bf[nf][1]);
            }

            if (k0 + ABKV - 1 > qlo) {
#pragma unroll
                for (int nf = 0; nf < 8; nf++) {
                    int cb = k0 + 8 * nf + 2 * (lane & 3);
                    if (cb     > qrow)     sacc[nf][0] = NEGINF;
                    if (cb + 1 > qrow)     sacc[nf][1] = NEGINF;
                    if (cb     > qrow + 8) sacc[nf][2] = NEGINF;
                    if (cb + 1 > qrow + 8) sacc[nf][3] = NEGINF;
                }
            }

            float mx1 = NEGINF, mx2 = NEGINF;
#pragma unroll
            for (int nf = 0; nf < 8; nf++) {
                mx1 = fmaxf(mx1, fmaxf(sacc[nf][0], sacc[nf][1]));
                mx2 = fmaxf(mx2, fmaxf(sacc[nf][2], sacc[nf][3]));
            }
            mx1 = fmaxf(mx1, __shfl_xor_sync(0xffffffffu, mx1, 1));
            mx1 = fmaxf(mx1, __shfl_xor_sync(0xffffffffu, mx1, 2));
            mx2 = fmaxf(mx2, __shfl_xor_sync(0xffffffffu, mx2, 1));
            mx2 = fmaxf(mx2, __shfl_xor_sync(0xffffffffu, mx2, 2));
            const float mn1 = fmaxf(m1, mx1), mn2 = fmaxf(m2, mx2);
            const float a1 = ex2f(m1 - mn1), a2 = ex2f(m2 - mn2);

            float s1 = 0.f, s2 = 0.f;
            {
                const int pr = 16 * w + (lane >> 2);
                const int pcb = 2 * (lane & 3);
#pragma unroll
                for (int nf = 0; nf < 8; nf++) {
                    float p0 = ex2f(sacc[nf][0] - mn1);
                    float p1 = ex2f(sacc[nf][1] - mn1);
                    float p2 = ex2f(sacc[nf][2] - mn2);
                    float p3 = ex2f(sacc[nf][3] - mn2);
                    s1 += p0 + p1;
                    s2 += p2 + p3;
                    *(float2*)&Pw[pr * P_STR + 8 * nf + pcb] =
                        make_float2(rtf32(p0), rtf32(p1));
                    *(float2*)&Pw[(pr + 8) * P_STR + 8 * nf + pcb] =
                        make_float2(rtf32(p2), rtf32(p3));
                }
            }
            s1 += __shfl_xor_sync(0xffffffffu, s1, 1);
            s1 += __shfl_xor_sync(0xffffffffu, s1, 2);
            s2 += __shfl_xor_sync(0xffffffffu, s2, 1);
            s2 += __shfl_xor_sync(0xffffffffu, s2, 2);
            l1 = l1 * a1 + s1;
            l2 = l2 * a2 + s2;
            m1 = mn1; m2 = mn2;

#pragma unroll
            for (int n = 0; n < 16; n++) {
                oacc[n][0] *= a1; oacc[n][1] *= a1;
                oacc[n][2] *= a2; oacc[n][3] *= a2;
            }
            __syncwarp();

            const int pr = 16 * w + (lane >> 2);
#pragma unroll
            for (int kk = 0; kk < 8; kk++) {
                uint32_t pf[4];
                int pbase = pr * P_STR + 8 * kk + (lane & 3);
                pf[0] = *(const uint32_t*)&Pw[pbase];
                pf[1] = *(const uint32_t*)&Pw[pbase + 8 * P_STR];
                pf[2] = *(const uint32_t*)&Pw[pbase + 4];
                pf[3] = *(const uint32_t*)&Pw[pbase + 8 * P_STR + 4];
#pragma unroll
                for (int nf = 0; nf < 16; nf++) {
                    int a = (8 * kk + (lane & 3)) * KV_STR + 8 * nf + (lane >> 2);
                    uint32_t v0 = *(const uint32_t*)&Vb[a];
                    uint32_t v1 = *(const uint32_t*)&Vb[a + 4 * KV_STR];
                    mma8(oacc[nf], pf, v0, v1);
                }
            }
        }
        __syncthreads();
    }

    const float li1 = 1.f / l1, li2 = 1.f / l2;
    float* Ob = O + ((size_t)(b * SS + qrow)) * HH + h * HD;
#pragma unroll
    for (int nf = 0; nf < 16; nf++) {
        int col = 8 * nf + 2 * (lane & 3);
        *(float2*)(Ob + col) =
            make_float2(rtf32(oacc[nf][0] * li1), rtf32(oacc[nf][1] * li1));
        *(float2*)(Ob + (size_t)8 * HH + col) =
            make_float2(rtf32(oacc[nf][2] * li2), rtf32(oacc[nf][3] * li2));
    }
}

// ---------------------------------------------------------------------------
// kernel_launch
// ---------------------------------------------------------------------------
extern "C" void kernel_launch(void* const* d_in, const int* in_sizes, int n_in,
                              void* d_out, int out_size)
{
    const float* hs   = (const float*)d_in[0];
    const float* cosp = (const float*)d_in[1];
    const float* sinp = (const float*)d_in[2];
    const float* Wq   = (const float*)d_in[3];
    const float* Wk   = (const float*)d_in[4];
    const float* Wv   = (const float*)d_in[5];
    const float* Wd   = (const float*)d_in[6];
    float* out = (float*)d_out;

    float *pQ, *pK, *pV, *pO, *pKP, *pVP, *pHSR, *pWQR, *pWDR;
    cudaGetSymbolAddress((void**)&pQ, g_Q);
    cudaGetSymbolAddress((void**)&pK, g_K);
    cudaGetSymbolAddress((void**)&pV, g_V);
    cudaGetSymbolAddress((void**)&pO, g_O);
    cudaGetSymbolAddress((void**)&pKP, g_KP);
    cudaGetSymbolAddress((void**)&pVP, g_VP);
    cudaGetSymbolAddress((void**)&pHSR, g_HSR);
    cudaGetSymbolAddress((void**)&pWQR, g_WQR);
    cudaGetSymbolAddress((void**)&pWDR, g_WDR);

    const int gsmem = 4 * 128 * TSTR * 4;             // 73728 B
    const int asmem = ATT_SMEM_FLOATS * 4;            // 174080 B
    cudaFuncSetAttribute(gemm_big, cudaFuncAttributeMaxDynamicSharedMemorySize, BIG_SMEM);
    cudaFuncSetAttribute(gemm_mma, cudaFuncAttributeMaxDynamicSharedMemorySize, gsmem);
    cudaFuncSetAttribute(attn_mma, cudaFuncAttributeMaxDynamicSharedMemorySize, asmem);

    const int bign = NTOK * HH;   // 16.7M
    const int kvn  = NTOK * HD;   // 524288

    // Pre-round inputs for cp.async GEMMs
    round_tf32<<<bign / 4 / 256, 256>>>(hs, pHSR, bign);
    round_tf32<<<bign / 4 / 256, 256>>>(Wq, pWQR, bign);
    round_tf32<<<bign / 4 / 256, 256>>>(Wd, pWDR, bign);

    // Q projection (big tile, cp.async)
    gemm_big<<<dim3(HH / 256, NTOK / 128), 256, BIG_SMEM>>>(pHSR, pWQR, pQ);

    // K/V projections (split-K; rounds internally, rounded input is idempotent)
    gemm_mma<<<dim3(1, NTOK / 128, NSPLIT), 256, gsmem>>>(pHSR, Wk, pKP, NTOK, HD, HH, HH / NSPLIT);
    gemm_mma<<<dim3(1, NTOK / 128, NSPLIT), 256, gsmem>>>(pHSR, Wv, pVP, NTOK, HD, HH, HH / NSPLIT);
    reduce_split<<<kvn / 4 / 256, 256>>>(pKP, pK, kvn, 0);
    reduce_split<<<kvn / 4 / 256, 256>>>(pVP, pV, kvn, 1);

    // RoPE
    rope_q_kernel<<<(NTOK * NH * 64) / 256, 256>>>(pQ, cosp, sinp);
    rope_k_kernel<<<(NTOK * 64) / 256, 256>>>(pK, cosp, sinp);

    // Tensor-core flash attention (writes O tf32-rounded)
    attn_mma<<<dim3(SS / ABQ, NH, BB), 256, asmem>>>(pQ, pK, pV, pO);

    // Output projection (big tile, cp.async)
    gemm_big<<<dim3(HH / 256, NTOK / 128), 256, BIG_SMEM>>>(pO, pWDR, out);
}

// round 15
// speedup vs baseline: 1.0001x; 1.0001x over previous
#include <cuda_runtime.h>
#include <cuda_bf16.h>
#include <cstdint>
#include <cstddef>

// Problem constants
#define BB 2
#define SS 2048
#define HH 4096
#define NH 32
#define HD 128
#define NTOK (BB * SS)   // 4096
#define NSPLIT 8

// ---------------------------------------------------------------------------
// Scratch (allocation-free: __device__ globals)
// ---------------------------------------------------------------------------
__device__ float g_Q[NTOK * HH];            // 64 MB
__device__ float g_K[NTOK * HD];            // 2 MB
__device__ float g_V[NTOK * HD];            // 2 MB
__device__ float g_O[NTOK * HH];            // 64 MB (attention out, tf32-rounded)
__device__ float g_KP[NSPLIT * NTOK * HD];  // split-K partials
__device__ float g_VP[NSPLIT * NTOK * HD];
__device__ float g_HSR[NTOK * HH];          // tf32-rounded hidden states
__device__ float g_WQR[HH * HH];            // tf32-rounded Wq
__device__ float g_WDR[HH * HH];            // tf32-rounded Wd

__device__ __forceinline__ uint32_t f2tf32(float x) {
    uint32_t y;
    asm("cvt.rna.tf32.f32 %0, %1;" : "=r"(y) : "f"(x));
    return y;
}
__device__ __forceinline__ float rtf32(float x) {
    return __uint_as_float(f2tf32(x));
}
__device__ __forceinline__ float ex2f(float x) {
    float y;
    asm("ex2.approx.ftz.f32 %0, %1;" : "=f"(y) : "f"(x));
    return y;
}
__device__ __forceinline__ uint32_t smem_u32(const void* p) {
    uint32_t a;
    asm("{ .reg .u64 t; cvta.to.shared.u64 t, %1; cvt.u32.u64 %0, t; }" : "=r"(a) : "l"(p));
    return a;
}
__device__ __forceinline__ void cp16(uint32_t dst, const void* src) {
    asm volatile("cp.async.cg.shared.global [%0], [%1], 16;" :: "r"(dst), "l"(src) : "memory");
}
__device__ __forceinline__ void cp_commit() {
    asm volatile("cp.async.commit_group;" ::: "memory");
}
__device__ __forceinline__ void mma8(float* d, const uint32_t* a, uint32_t b0, uint32_t b1) {
    asm volatile(
        "mma.sync.aligned.m16n8k8.row.col.f32.tf32.tf32.f32 "
        "{%0,%1,%2,%3}, {%4,%5,%6,%7}, {%8,%9}, {%0,%1,%2,%3};"
        : "+f"(d[0]), "+f"(d[1]), "+f"(d[2]), "+f"(d[3])
        : "r"(a[0]), "r"(a[1]), "r"(a[2]), "r"(a[3]), "r"(b0), "r"(b1));
}

// ---------------------------------------------------------------------------
// tf32 pre-round: out[i] = rtf32(in[i])
// ---------------------------------------------------------------------------
__global__ __launch_bounds__(256)
void round_tf32(const float* __restrict__ in, float* __restrict__ out, int n)
{
    int i = (blockIdx.x * blockDim.x + threadIdx.x) * 4;
    if (i >= n) return;
    float4 v = *(const float4*)(in + i);
    *(float4*)(out + i) = make_float4(rtf32(v.x), rtf32(v.y), rtf32(v.z), rtf32(v.w));
}

// ---------------------------------------------------------------------------
// Big GEMM (NT), inputs PRE-ROUNDED to tf32: C[m,n] = sum_k A[m,k]*W[n,k]
// BM=128, BN=256, BK=32, 256 threads, 8 warps (2x4), warp tile 64x64.
// 3-stage cp.async pipeline. M=N=K=4096.
// ---------------------------------------------------------------------------
#define NBK 32
#define NTSTR 36
#define BIG_STG ((128 + 256) * NTSTR)          // floats per stage (13824)
#define BIG_SMEM (3 * BIG_STG * 4)             // 165888 B

__global__ __launch_bounds__(256)
void gemm_big(const float* __restrict__ A, const float* __restrict__ W,
              float* __restrict__ C)
{
    constexpr int K = HH, N = HH;
    extern __shared__ float smem[];

    const int tid = threadIdx.x;
    const int lane = tid & 31, wid = tid >> 5;
    const int wm = wid & 1, wn = wid >> 1;           // 2 x 4 warps
    const int m0 = blockIdx.y * 128, n0 = blockIdx.x * 256;
    const uint32_t sb = smem_u32(smem);

    const float* Ag0 = A + (size_t)m0 * K;
    const float* Wg0 = W + (size_t)n0 * K;

    float d[4][8][4];
#pragma unroll
    for (int i = 0; i < 4; i++)
#pragma unroll
        for (int j = 0; j < 8; j++)
#pragma unroll
            for (int q = 0; q < 4; q++) d[i][j][q] = 0.f;

    const int nch = K / NBK;   // 128
    const int lrA = tid >> 3, lsg = (tid & 7) << 2;

    auto issue = [&](int c) {
        const int s = c % 3;
        const uint32_t dA = sb + (uint32_t)(s * BIG_STG) * 4;
        const uint32_t dB = dA + 128 * NTSTR * 4;
        const float* Ag = Ag0 + c * NBK;
        const float* Wg = Wg0 + c * NBK;
#pragma unroll
        for (int u = 0; u < 4; u++) {
            int r = lrA + u * 32;
            cp16(dA + (uint32_t)(r * NTSTR + lsg) * 4, Ag + (size_t)r * K + lsg);
        }
#pragma unroll
        for (int u = 0; u < 8; u++) {
            int r = lrA + u * 32;
            cp16(dB + (uint32_t)(r * NTSTR + lsg) * 4, Wg + (size_t)r * K + lsg);
        }
        cp_commit();
    };

    issue(0);
    issue(1);

    for (int c = 0; c < nch; c++) {
        if (c == nch - 1) {
            asm volatile("cp.async.wait_group 0;" ::: "memory");
        } else {
            asm volatile("cp.async.wait_group 1;" ::: "memory");
        }
        __syncthreads();
        if (c + 2 < nch) issue(c + 2);

        const float* as = smem + (c % 3) * BIG_STG;
        const float* bs = as + 128 * NTSTR;
#pragma unroll
        for (int ks = 0; ks < 4; ks++) {
            const int kb = ks * 8 + (lane & 3);
            uint32_t af[4][4];
#pragma unroll
            for (int i = 0; i < 4; i++) {
                int r = wm * 64 + i * 16 + (lane >> 2);
                af[i][0] = *(const uint32_t*)&as[r * NTSTR + kb];
                af[i][1] = *(const uint32_t*)&as[(r + 8) * NTSTR + kb];
                af[i][2] = *(const uint32_t*)&as[r * NTSTR + kb + 4];
                af[i][3] = *(const uint32_t*)&as[(r + 8) * NTSTR + kb + 4];
            }
#pragma unroll
            for (int j = 0; j < 8; j++) {
                int n = wn * 64 + j * 8 + (lane >> 2);
                uint32_t b0 = *(const uint32_t*)&bs[n * NTSTR + kb];
                uint32_t b1 = *(const uint32_t*)&bs[n * NTSTR + kb + 4];
#pragma unroll
                for (int i = 0; i < 4; i++)
                    mma8(d[i][j], af[i], b0, b1);
            }
        }
        __syncthreads();
    }

#pragma unroll
    for (int i = 0; i < 4; i++) {
        int r0 = m0 + wm * 64 + i * 16 + (lane >> 2);
#pragma unroll
        for (int j = 0; j < 8; j++) {
            int cc = n0 + wn * 64 + j * 8 + (lane & 3) * 2;
            *(float2*)(C + (size_t)r0 * N + cc)       = make_float2(d[i][j][0], d[i][j][1]);
            *(float2*)(C + (size_t)(r0 + 8) * N + cc) = make_float2(d[i][j][2], d[i][j][3]);
        }
    }
}

// ---------------------------------------------------------------------------
// Small GEMM (NT) with split-K (for K/V projections), rounds inputs itself.
// ---------------------------------------------------------------------------
#define GBK 32
#define TSTR 36

__global__ __launch_bounds__(256)
void gemm_mma(const float* __restrict__ A, const float* __restrict__ W,
              float* __restrict__ C, int M, int N, int K, int kspl)
{
    extern __shared__ float smem[];
    float* As[2] = { smem,                  smem + 128 * TSTR };
    float* Bs[2] = { smem + 2 * 128 * TSTR, smem + 3 * 128 * TSTR };

    const int tid = threadIdx.x;
    const int lane = tid & 31, wid = tid >> 5;
    const int wm = wid & 1, wn = wid >> 1;
    const int m0 = blockIdx.y * 128, n0 = blockIdx.x * 128;
    const int z = blockIdx.z;

    const int lr = tid >> 3;
    const int lc = (tid & 7) << 2;

    const float* Ag = A + (size_t)m0 * K + (size_t)z * kspl;
    const float* Wg = W + (size_t)n0 * K + (size_t)z * kspl;
    C += (size_t)z * M * N;

    float d[4][4][4];
#pragma unroll
    for (int i = 0; i < 4; i++)
#pragma unroll
        for (int j = 0; j < 4; j++)
#pragma unroll
            for (int q = 0; q < 4; q++) d[i][j][q] = 0.f;

    const int nch = kspl / GBK;
    float4 pa[4], pb[4];

#pragma unroll
    for (int u = 0; u < 4; u++) {
        int r = lr + u * 32;
        pa[u] = *(const float4*)(Ag + (size_t)r * K + lc);
        pb[u] = *(const float4*)(Wg + (size_t)r * K + lc);
    }
#pragma unroll
    for (int u = 0; u < 4; u++) {
        int r = lr + u * 32;
        *(float4*)(As[0] + r * TSTR + lc) =
            make_float4(rtf32(pa[u].x), rtf32(pa[u].y), rtf32(pa[u].z), rtf32(pa[u].w));
        *(float4*)(Bs[0] + r * TSTR + lc) =
            make_float4(rtf32(pb[u].x), rtf32(pb[u].y), rtf32(pb[u].z), rtf32(pb[u].w));
    }
    __syncthreads();

    for (int c = 0; c < nch; c++) {
        const int s = c & 1;

        if (c + 1 < nch) {
            const float* Agn = Ag + (c + 1) * GBK;
            const float* Wgn = Wg + (c + 1) * GBK;
#pragma unroll
            for (int u = 0; u < 4; u++) {
                int r = lr + u * 32;
                pa[u] = *(const float4*)(Agn + (size_t)r * K + lc);
                pb[u] = *(const float4*)(Wgn + (size_t)r * K + lc);
            }
        }

        const float* as = As[s];
        const float* bs = Bs[s];
#pragma unroll
        for (int ks = 0; ks < 4; ks++) {
            const int kb = ks * 8 + (lane & 3);
            uint32_t af[4][4];
#pragma unroll
            for (int i = 0; i < 4; i++) {
                int r = wm * 64 + i * 16 + (lane >> 2);
                af[i][0] = *(const uint32_t*)&as[r * TSTR + kb];
                af[i][1] = *(const uint32_t*)&as[(r + 8) * TSTR + kb];
                af[i][2] = *(const uint32_t*)&as[r * TSTR + kb + 4];
                af[i][3] = *(const uint32_t*)&as[(r + 8) * TSTR + kb + 4];
            }
            uint32_t bf[4][2];
#pragma unroll
            for (int j = 0; j < 4; j++) {
                int n = wn * 32 + j * 8 + (lane >> 2);
                bf[j][0] = *(const uint32_t*)&bs[n * TSTR + kb];
                bf[j][1] = *(const uint32_t*)&bs[n * TSTR + kb + 4];
            }
#pragma unroll
            for (int i = 0; i < 4; i++)
#pragma unroll
                for (int j = 0; j < 4; j++)
                    mma8(d[i][j], af[i], bf[j][0], bf[j][1]);
        }

        if (c + 1 < nch) {
            const int s2 = s ^ 1;
#pragma unroll
            for (int u = 0; u < 4; u++) {
                int r = lr + u * 32;
                *(float4*)(As[s2] + r * TSTR + lc) =
                    make_float4(rtf32(pa[u].x), rtf32(pa[u].y), rtf32(pa[u].z), rtf32(pa[u].w));
                *(float4*)(Bs[s2] + r * TSTR + lc) =
                    make_float4(rtf32(pb[u].x), rtf32(pb[u].y), rtf32(pb[u].z), rtf32(pb[u].w));
            }
        }
        __syncthreads();
    }

#pragma unroll
    for (int i = 0; i < 4; i++) {
        int r0 = m0 + wm * 64 + i * 16 + (lane >> 2);
#pragma unroll
        for (int j = 0; j < 4; j++) {
            int cc = n0 + wn * 32 + j * 8 + (lane & 3) * 2;
            *(float2*)(C + (size_t)r0 * N + cc)       = make_float2(d[i][j][0], d[i][j][1]);
            *(float2*)(C + (size_t)(r0 + 8) * N + cc) = make_float2(d[i][j][2], d[i][j][3]);
        }
    }
}

// ---------------------------------------------------------------------------
// Split-K reduction
// ---------------------------------------------------------------------------
__global__ __launch_bounds__(256)
void reduce_split(const float* __restrict__ part, float* __restrict__ out,
                  int n, int rnd)
{
    int i = (blockIdx.x * blockDim.x + threadIdx.x) * 4;
    if (i >= n) return;
    float4 acc = *(const float4*)(part + i);
#pragma unroll
    for (int s = 1; s < NSPLIT; s++) {
        float4 v = *(const float4*)(part + (size_t)s * n + i);
        acc.x += v.x; acc.y += v.y; acc.z += v.z; acc.w += v.w;
    }
    if (rnd) {
        acc.x = rtf32(acc.x); acc.y = rtf32(acc.y);
        acc.z = rtf32(acc.z); acc.w = rtf32(acc.w);
    }
    *(float4*)(out + i) = acc;
}

// ---------------------------------------------------------------------------
// RoPE
// ---------------------------------------------------------------------------
#define QSC (0.08838834764831845f * 1.4426950408889634f)

__global__ __launch_bounds__(256) void rope_q_kernel(
    float* __restrict__ Q, const float* __restrict__ cosp, const float* __restrict__ sinp)
{
    int i = blockIdx.x * blockDim.x + threadIdx.x;
    if (i >= NTOK * NH * 64) return;
    int d = i & 63;
    int h = (i >> 6) & 31;
    int t = i >> 11;
    int s = t & (SS - 1);
    float* q = Q + (size_t)t * HH + h * HD;
    float c1 = cosp[s * HD + d],      s1 = sinp[s * HD + d];
    float c2 = cosp[s * HD + d + 64], s2 = sinp[s * HD + d + 64];
    float x1 = q[d], x2 = q[d + 64];
    q[d]      = rtf32((x1 * c1 - x2 * s1) * QSC);
    q[d + 64] = rtf32((x2 * c2 + x1 * s2) * QSC);
}

__global__ __launch_bounds__(256) void rope_k_kernel(
    float* __restrict__ K, const float* __restrict__ cosp, const float* __restrict__ sinp)
{
    int i = blockIdx.x * blockDim.x + threadIdx.x;
    if (i >= NTOK * 64) return;
    int d = i & 63;
    int t = i >> 6;
    int s = t & (SS - 1);
    float* k = K + (size_t)t * HD;
    float c1 = cosp[s * HD + d],      s1 = sinp[s * HD + d];
    float c2 = cosp[s * HD + d + 64], s2 = sinp[s * HD + d + 64];
    float x1 = k[d], x2 = k[d + 64];
    k[d]      = rtf32(x1 * c1 - x2 * s1);
    k[d + 64] = rtf32(x2 * c2 + x1 * s2);
}

// ---------------------------------------------------------------------------
// Tensor-core flash attention (TF32 mma.sync), causal, MQA.
// O written tf32-rounded (Wd's cp.async path needs pre-rounded input).
// ---------------------------------------------------------------------------
#define ABQ 128
#define ABKV 64
#define KV_STR 136
#define P_STR 68
#define BUF_FLOATS 17408
#define P_OFF (2 * BUF_FLOATS)
#define ATT_SMEM_FLOATS (P_OFF + 128 * P_STR)
#define NEGINF (-1e30f)

__global__ __launch_bounds__(256)
void attn_mma(const float* __restrict__ Q, const float* __restrict__ Kg,
              const float* __restrict__ Vg, float* __restrict__ O)
{
    extern __shared__ float sm[];
    const int tid = threadIdx.x;
    const int lane = tid & 31, w = tid >> 5;
    const int qb = (int)gridDim.x - 1 - (int)blockIdx.x;
    const int h = blockIdx.y, b = blockIdx.z;
    const int q0 = qb * ABQ;
    const uint32_t sb = smem_u32(sm);

    {
        const float* Qg = Q + ((size_t)(b * SS + q0)) * HH + h * HD;
#pragma unroll
        for (int j = 0; j < 16; j++) {
            int i = tid + j * 256;
            int r = i >> 5, c = (i & 31) * 4;
            *(float4*)&sm[r * KV_STR + c] = *(const float4*)(Qg + (size_t)r * HH + c);
        }
    }
    __syncthreads();

    uint32_t qf[16][4];
    {
        const int r = 16 * w + (lane >> 2);
#pragma unroll
        for (int ks = 0; ks < 16; ks++) {
            int base = r * KV_STR + 8 * ks + (lane & 3);
            qf[ks][0] = *(const uint32_t*)&sm[base];
            qf[ks][1] = *(const uint32_t*)&sm[base + 8 * KV_STR];
            qf[ks][2] = *(const uint32_t*)&sm[base + 4];
            qf[ks][3] = *(const uint32_t*)&sm[base + 8 * KV_STR + 4];
        }
    }
    __syncthreads();

    float oacc[16][4];
#pragma unroll
    for (int n = 0; n < 16; n++)
#pragma unroll
        for (int q = 0; q < 4; q++) oacc[n][q] = 0.f;

    float m1 = NEGINF, m2 = NEGINF, l1 = 0.f, l2 = 0.f;

    const int ntile = (q0 + ABQ) / ABKV;
    const float* Kbase = Kg + (size_t)(b * SS) * HD;
    const float* Vbase = Vg + (size_t)(b * SS) * HD;
    const int qlo = q0 + 16 * w;
    const int qrow = qlo + (lane >> 2);

    {
#pragma unroll
        for (int j = 0; j < 8; j++) {
            int r = 8 * w + j;
            cp16(sb + (r * KV_STR + lane * 4) * 4, Kbase + (size_t)r * HD + lane * 4);
            cp16(sb + (8704 + r * KV_STR + lane * 4) * 4, Vbase + (size_t)r * HD + lane * 4);
        }
        cp_commit();
    }

    for (int t = 0; t < ntile; t++) {
        const int k0 = t * ABKV;

        if (t + 1 < ntile) {
            const int bufo = ((t + 1) & 1) * BUF_FLOATS;
            const float* Ks = Kbase + (size_t)(k0 + ABKV) * HD;
            const float* Vs = Vbase + (size_t)(k0 + ABKV) * HD;
#pragma unroll
            for (int j = 0; j < 8; j++) {
                int r = 8 * w + j;
                cp16(sb + (bufo + r * KV_STR + lane * 4) * 4, Ks + (size_t)r * HD + lane * 4);
                cp16(sb + (bufo + 8704 + r * KV_STR + lane * 4) * 4, Vs + (size_t)r * HD + lane * 4);
            }
            cp_commit();
            asm volatile("cp.async.wait_group 1;" ::: "memory");
        } else {
            asm volatile("cp.async.wait_group 0;" ::: "memory");
        }
        __syncthreads();

        if (k0 <= qlo + 15) {
            const float* Kb = sm + (t & 1) * BUF_FLOATS;
            const float* Vb = Kb + 8704;
            float* Pw = sm + P_OFF;

            float sacc[8][4];
#pragma unroll
            for (int n = 0; n < 8; n++)
#pragma unroll
                for (int q = 0; q < 4; q++) sacc[n][q] = 0.f;

#pragma unroll
            for (int ks = 0; ks < 16; ks++) {
                uint32_t bf[8][2];
#pragma unroll
                for (int nf = 0; nf < 8; nf++) {
                    int a = (8 * nf + (lane >> 2)) * KV_STR + 8 * ks + (lane & 3);
                    bf[nf][0] = *(const uint32_t*)&Kb[a];
                    bf[nf][1] = *(const uint32_t*)&Kb[a + 4];
                }
#pragma unroll
                for (int nf = 0; nf < 8; nf++)
                    mma8(sacc[nf], qf[ks], bf[nf][0], bf[nf][1]);
            }

            if (k0 + ABKV - 1 > qlo) {
#pragma unroll
                for (int nf = 0; nf < 8; nf++) {
                    int cb = k0 + 8 * nf + 2 * (lane & 3);
                    if (cb     > qrow)     sacc[nf][0] = NEGINF;
                    if (cb + 1 > qrow)     sacc[nf][1] = NEGINF;
                    if (cb     > qrow + 8) sacc[nf][2] = NEGINF;
                    if (cb + 1 > qrow + 8) sacc[nf][3] = NEGINF;
                }
            }

            float mx1 = NEGINF, mx2 = NEGINF;
#pragma unroll
            for (int nf = 0; nf < 8; nf++) {
                mx1 = fmaxf(mx1, fmaxf(sacc[nf][0], sacc[nf][1]));
                mx2 = fmaxf(mx2, fmaxf(sacc[nf][2], sacc[nf][3]));
            }
            mx1 = fmaxf(mx1, __shfl_xor_sync(0xffffffffu, mx1, 1));
            mx1 = fmaxf(mx1, __shfl_xor_sync(0xffffffffu, mx1, 2));
            mx2 = fmaxf(mx2, __shfl_xor_sync(0xffffffffu, mx2, 1));
            mx2 = fmaxf(mx2, __shfl_xor_sync(0xffffffffu, mx2, 2));
            const float mn1 = fmaxf(m1, mx1), mn2 = fmaxf(m2, mx2);
            const float a1 = ex2f(m1 - mn1), a2 = ex2f(m2 - mn2);

            float s1 = 0.f, s2 = 0.f;
            {
                const int pr = 16 * w + (lane >> 2);
                const int pcb = 2 * (lane & 3);
#pragma unroll
                for (int nf = 0; nf < 8; nf++) {
                    float p0 = ex2f(sacc[nf][0] - mn1);
                    float p1 = ex2f(sacc[nf][1] - mn1);
                    float p2 = ex2f(sacc[nf][2] - mn2);
                    float p3 = ex2f(sacc[nf][3] - mn2);
                    s1 += p0 + p1;
                    s2 += p2 + p3;
                    *(float2*)&Pw[pr * P_STR + 8 * nf + pcb] =
                        make_float2(rtf32(p0), rtf32(p1));
                    *(float2*)&Pw[(pr + 8) * P_STR + 8 * nf + pcb] =
                        make_float2(rtf32(p2), rtf32(p3));
                }
            }
            s1 += __shfl_xor_sync(0xffffffffu, s1, 1);
            s1 += __shfl_xor_sync(0xffffffffu, s1, 2);
            s2 += __shfl_xor_sync(0xffffffffu, s2, 1);
            s2 += __shfl_xor_sync(0xffffffffu, s2, 2);
            l1 = l1 * a1 + s1;
            l2 = l2 * a2 + s2;
            m1 = mn1; m2 = mn2;

#pragma unroll
            for (int n = 0; n < 16; n++) {
                oacc[n][0] *= a1; oacc[n][1] *= a1;
                oacc[n][2] *= a2; oacc[n][3] *= a2;
            }
            __syncwarp();

            const int pr = 16 * w + (lane >> 2);
#pragma unroll
            for (int kk = 0; kk < 8; kk++) {
                uint32_t pf[4];
                int pbase = pr * P_STR + 8 * kk + (lane & 3);
                pf[0] = *(const uint32_t*)&Pw[pbase];
                pf[1] = *(const uint32_t*)&Pw[pbase + 8 * P_STR];
                pf[2] = *(const uint32_t*)&Pw[pbase + 4];
                pf[3] = *(const uint32_t*)&Pw[pbase + 8 * P_STR + 4];
#pragma unroll
                for (int nf = 0; nf < 16; nf++) {
                    int a = (8 * kk + (lane & 3)) * KV_STR + 8 * nf + (lane >> 2);
                    uint32_t v0 = *(const uint32_t*)&Vb[a];
                    uint32_t v1 = *(const uint32_t*)&Vb[a + 4 * KV_STR];
                    mma8(oacc[nf], pf, v0, v1);
                }
            }
        }
        __syncthreads();
    }

    const float li1 = 1.f / l1, li2 = 1.f / l2;
    float* Ob = O + ((size_t)(b * SS + qrow)) * HH + h * HD;
#pragma unroll
    for (int nf = 0; nf < 16; nf++) {
        int col = 8 * nf + 2 * (lane & 3);
        *(float2*)(Ob + col) =
            make_float2(rtf32(oacc[nf][0] * li1), rtf32(oacc[nf][1] * li1));
        *(float2*)(Ob + (size_t)8 * HH + col) =
            make_float2(rtf32(oacc[nf][2] * li2), rtf32(oacc[nf][3] * li2));
    }
}

// ---------------------------------------------------------------------------
// kernel_launch
// ---------------------------------------------------------------------------
extern "C" void kernel_launch(void* const* d_in, const int* in_sizes, int n_in,
                              void* d_out, int out_size)
{
    const float* hs   = (const float*)d_in[0];
    const float* cosp = (const float*)d_in[1];
    const float* sinp = (const float*)d_in[2];
    const float* Wq   = (const float*)d_in[3];
    const float* Wk   = (const float*)d_in[4];
    const float* Wv   = (const float*)d_in[5];
    const float* Wd   = (const float*)d_in[6];
    float* out = (float*)d_out;

    float *pQ, *pK, *pV, *pO, *pKP, *pVP, *pHSR, *pWQR, *pWDR;
    cudaGetSymbolAddress((void**)&pQ, g_Q);
    cudaGetSymbolAddress((void**)&pK, g_K);
    cudaGetSymbolAddress((void**)&pV, g_V);
    cudaGetSymbolAddress((void**)&pO, g_O);
    cudaGetSymbolAddress((void**)&pKP, g_KP);
    cudaGetSymbolAddress((void**)&pVP, g_VP);
    cudaGetSymbolAddress((void**)&pHSR, g_HSR);
    cudaGetSymbolAddress((void**)&pWQR, g_WQR);
    cudaGetSymbolAddress((void**)&pWDR, g_WDR);

    const int gsmem = 4 * 128 * TSTR * 4;             // 73728 B
    const int asmem = ATT_SMEM_FLOATS * 4;            // 174080 B
    cudaFuncSetAttribute(gemm_big, cudaFuncAttributeMaxDynamicSharedMemorySize, BIG_SMEM);
    cudaFuncSetAttribute(gemm_mma, cudaFuncAttributeMaxDynamicSharedMemorySize, gsmem);
    cudaFuncSetAttribute(attn_mma, cudaFuncAttributeMaxDynamicSharedMemorySize, asmem);

    const int bign = NTOK * HH;   // 16.7M
    const int kvn  = NTOK * HD;   // 524288

    // Pre-round inputs for cp.async GEMMs
    round_tf32<<<bign / 4 / 256, 256>>>(hs, pHSR, bign);
    round_tf32<<<bign / 4 / 256, 256>>>(Wq, pWQR, bign);
    round_tf32<<<bign / 4 / 256, 256>>>(Wd, pWDR, bign);

    // Q projection (big tile, cp.async)
    gemm_big<<<dim3(HH / 256, NTOK / 128), 256, BIG_SMEM>>>(pHSR, pWQR, pQ);

    // K/V projections (split-K; rounds internally, rounded input is idempotent)
    gemm_mma<<<dim3(1, NTOK / 128, NSPLIT), 256, gsmem>>>(pHSR, Wk, pKP, NTOK, HD, HH, HH / NSPLIT);
    gemm_mma<<<dim3(1, NTOK / 128, NSPLIT), 256, gsmem>>>(pHSR, Wv, pVP, NTOK, HD, HH, HH / NSPLIT);
    reduce_split<<<kvn / 4 / 256, 256>>>(pKP, pK, kvn, 0);
    reduce_split<<<kvn / 4 / 256, 256>>>(pVP, pV, kvn, 1);

    // RoPE
    rope_q_kernel<<<(NTOK * NH * 64) / 256, 256>>>(pQ, cosp, sinp);
    rope_k_kernel<<<(NTOK * 64) / 256, 256>>>(pK, cosp, sinp);

    // Tensor-core flash attention (writes O tf32-rounded)
    attn_mma<<<dim3(SS / ABQ, NH, BB), 256, asmem>>>(pQ, pK, pV, pO);

    // Output projection (big tile, cp.async)
    gemm_big<<<dim3(HH / 256, NTOK / 128), 256, BIG_SMEM>>>(pO, pWDR, out);
}

// round 16
// speedup vs baseline: 1.0012x; 1.0010x over previous
#include <cuda_runtime.h>
#include <cuda_bf16.h>
#include <cstdint>
#include <cstddef>

// Problem constants
#define BB 2
#define SS 2048
#define HH 4096
#define NH 32
#define HD 128
#define NTOK (BB * SS)   // 4096
#define NSPLIT 8

// ---------------------------------------------------------------------------
// Scratch (allocation-free: __device__ globals)
// ---------------------------------------------------------------------------
__device__ float g_Q[NTOK * HH];            // 64 MB
__device__ float g_K[NTOK * HD];            // 2 MB
__device__ float g_V[NTOK * HD];            // 2 MB
__device__ float g_O[NTOK * HH];            // 64 MB (attention out, tf32-rounded)
__device__ float g_KP[NSPLIT * NTOK * HD];  // split-K partials
__device__ float g_VP[NSPLIT * NTOK * HD];
__device__ float g_HSR[NTOK * HH];          // tf32-rounded hidden states
__device__ float g_WQR[HH * HH];            // tf32-rounded Wq
__device__ float g_WDR[HH * HH];            // tf32-rounded Wd

__device__ __forceinline__ uint32_t f2tf32(float x) {
    uint32_t y;
    asm("cvt.rna.tf32.f32 %0, %1;" : "=r"(y) : "f"(x));
    return y;
}
__device__ __forceinline__ float rtf32(float x) {
    return __uint_as_float(f2tf32(x));
}
__device__ __forceinline__ float ex2f(float x) {
    float y;
    asm("ex2.approx.ftz.f32 %0, %1;" : "=f"(y) : "f"(x));
    return y;
}
__device__ __forceinline__ uint32_t smem_u32(const void* p) {
    uint32_t a;
    asm("{ .reg .u64 t; cvta.to.shared.u64 t, %1; cvt.u32.u64 %0, t; }" : "=r"(a) : "l"(p));
    return a;
}
__device__ __forceinline__ void cp16(uint32_t dst, const void* src) {
    asm volatile("cp.async.cg.shared.global [%0], [%1], 16;" :: "r"(dst), "l"(src) : "memory");
}
__device__ __forceinline__ void cp_commit() {
    asm volatile("cp.async.commit_group;" ::: "memory");
}
__device__ __forceinline__ void mma8(float* d, const uint32_t* a, uint32_t b0, uint32_t b1) {
    asm volatile(
        "mma.sync.aligned.m16n8k8.row.col.f32.tf32.tf32.f32 "
        "{%0,%1,%2,%3}, {%4,%5,%6,%7}, {%8,%9}, {%0,%1,%2,%3};"
        : "+f"(d[0]), "+f"(d[1]), "+f"(d[2]), "+f"(d[3])
        : "r"(a[0]), "r"(a[1]), "r"(a[2]), "r"(a[3]), "r"(b0), "r"(b1));
}

// ---------------------------------------------------------------------------
// tf32 pre-round: out[i] = rtf32(in[i])
// ---------------------------------------------------------------------------
__global__ __launch_bounds__(256)
void round_tf32(const float* __restrict__ in, float* __restrict__ out, int n)
{
    int i = (blockIdx.x * blockDim.x + threadIdx.x) * 4;
    if (i >= n) return;
    float4 v = *(const float4*)(in + i);
    *(float4*)(out + i) = make_float4(rtf32(v.x), rtf32(v.y), rtf32(v.z), rtf32(v.w));
}

// ---------------------------------------------------------------------------
// Big GEMM (NT), inputs PRE-ROUNDED to tf32: C[m,n] = sum_k A[m,k]*W[n,k]
// BM=128, BN=256, BK=32, 256 threads, 8 warps (2x4), warp tile 64x64.
// 3-stage cp.async pipeline. M=N=K=4096.
// ---------------------------------------------------------------------------
#define NBK 32
#define NTSTR 36
#define BIG_STG ((128 + 256) * NTSTR)          // floats per stage (13824)
#define BIG_SMEM (3 * BIG_STG * 4)             // 165888 B

__global__ __launch_bounds__(256)
void gemm_big(const float* __restrict__ A, const float* __restrict__ W,
              float* __restrict__ C)
{
    constexpr int K = HH, N = HH;
    extern __shared__ float smem[];

    const int tid = threadIdx.x;
    const int lane = tid & 31, wid = tid >> 5;
    const int wm = wid & 1, wn = wid >> 1;           // 2 x 4 warps
    const int m0 = blockIdx.y * 128, n0 = blockIdx.x * 256;
    const uint32_t sb = smem_u32(smem);

    const float* Ag0 = A + (size_t)m0 * K;
    const float* Wg0 = W + (size_t)n0 * K;

    float d[4][8][4];
#pragma unroll
    for (int i = 0; i < 4; i++)
#pragma unroll
        for (int j = 0; j < 8; j++)
#pragma unroll
            for (int q = 0; q < 4; q++) d[i][j][q] = 0.f;

    const int nch = K / NBK;   // 128
    const int lrA = tid >> 3, lsg = (tid & 7) << 2;

    auto issue = [&](int c) {
        const int s = c % 3;
        const uint32_t dA = sb + (uint32_t)(s * BIG_STG) * 4;
        const uint32_t dB = dA + 128 * NTSTR * 4;
        const float* Ag = Ag0 + c * NBK;
        const float* Wg = Wg0 + c * NBK;
#pragma unroll
        for (int u = 0; u < 4; u++) {
            int r = lrA + u * 32;
            cp16(dA + (uint32_t)(r * NTSTR + lsg) * 4, Ag + (size_t)r * K + lsg);
        }
#pragma unroll
        for (int u = 0; u < 8; u++) {
            int r = lrA + u * 32;
            cp16(dB + (uint32_t)(r * NTSTR + lsg) * 4, Wg + (size_t)r * K + lsg);
        }
        cp_commit();
    };

    issue(0);
    issue(1);

    for (int c = 0; c < nch; c++) {
        if (c == nch - 1) {
            asm volatile("cp.async.wait_group 0;" ::: "memory");
        } else {
            asm volatile("cp.async.wait_group 1;" ::: "memory");
        }
        __syncthreads();
        if (c + 2 < nch) issue(c + 2);

        const float* as = smem + (c % 3) * BIG_STG;
        const float* bs = as + 128 * NTSTR;
#pragma unroll
        for (int ks = 0; ks < 4; ks++) {
            const int kb = ks * 8 + (lane & 3);
            uint32_t af[4][4];
#pragma unroll
            for (int i = 0; i < 4; i++) {
                int r = wm * 64 + i * 16 + (lane >> 2);
                af[i][0] = *(const uint32_t*)&as[r * NTSTR + kb];
                af[i][1] = *(const uint32_t*)&as[(r + 8) * NTSTR + kb];
                af[i][2] = *(const uint32_t*)&as[r * NTSTR + kb + 4];
                af[i][3] = *(const uint32_t*)&as[(r + 8) * NTSTR + kb + 4];
            }
#pragma unroll
            for (int j = 0; j < 8; j++) {
                int n = wn * 64 + j * 8 + (lane >> 2);
                uint32_t b0 = *(const uint32_t*)&bs[n * NTSTR + kb];
                uint32_t b1 = *(const uint32_t*)&bs[n * NTSTR + kb + 4];
#pragma unroll
                for (int i = 0; i < 4; i++)
                    mma8(d[i][j], af[i], b0, b1);
            }
        }
        __syncthreads();
    }

#pragma unroll
    for (int i = 0; i < 4; i++) {
        int r0 = m0 + wm * 64 + i * 16 + (lane >> 2);
#pragma unroll
        for (int j = 0; j < 8; j++) {
            int cc = n0 + wn * 64 + j * 8 + (lane & 3) * 2;
            *(float2*)(C + (size_t)r0 * N + cc)       = make_float2(d[i][j][0], d[i][j][1]);
            *(float2*)(C + (size_t)(r0 + 8) * N + cc) = make_float2(d[i][j][2], d[i][j][3]);
        }
    }
}

// ---------------------------------------------------------------------------
// Small GEMM (NT) with split-K (for K/V projections), rounds inputs itself.
// ---------------------------------------------------------------------------
#define GBK 32
#define TSTR 36

__global__ __launch_bounds__(256)
void gemm_mma(const float* __restrict__ A, const float* __restrict__ W,
              float* __restrict__ C, int M, int N, int K, int kspl)
{
    extern __shared__ float smem[];
    float* As[2] = { smem,                  smem + 128 * TSTR };
    float* Bs[2] = { smem + 2 * 128 * TSTR, smem + 3 * 128 * TSTR };

    const int tid = threadIdx.x;
    const int lane = tid & 31, wid = tid >> 5;
    const int wm = wid & 1, wn = wid >> 1;
    const int m0 = blockIdx.y * 128, n0 = blockIdx.x * 128;
    const int z = blockIdx.z;

    const int lr = tid >> 3;
    const int lc = (tid & 7) << 2;

    const float* Ag = A + (size_t)m0 * K + (size_t)z * kspl;
    const float* Wg = W + (size_t)n0 * K + (size_t)z * kspl;
    C += (size_t)z * M * N;

    float d[4][4][4];
#pragma unroll
    for (int i = 0; i < 4; i++)
#pragma unroll
        for (int j = 0; j < 4; j++)
#pragma unroll
            for (int q = 0; q < 4; q++) d[i][j][q] = 0.f;

    const int nch = kspl / GBK;
    float4 pa[4], pb[4];

#pragma unroll
    for (int u = 0; u < 4; u++) {
        int r = lr + u * 32;
        pa[u] = *(const float4*)(Ag + (size_t)r * K + lc);
        pb[u] = *(const float4*)(Wg + (size_t)r * K + lc);
    }
#pragma unroll
    for (int u = 0; u < 4; u++) {
        int r = lr + u * 32;
        *(float4*)(As[0] + r * TSTR + lc) =
            make_float4(rtf32(pa[u].x), rtf32(pa[u].y), rtf32(pa[u].z), rtf32(pa[u].w));
        *(float4*)(Bs[0] + r * TSTR + lc) =
            make_float4(rtf32(pb[u].x), rtf32(pb[u].y), rtf32(pb[u].z), rtf32(pb[u].w));
    }
    __syncthreads();

    for (int c = 0; c < nch; c++) {
        const int s = c & 1;

        if (c + 1 < nch) {
            const float* Agn = Ag + (c + 1) * GBK;
            const float* Wgn = Wg + (c + 1) * GBK;
#pragma unroll
            for (int u = 0; u < 4; u++) {
                int r = lr + u * 32;
                pa[u] = *(const float4*)(Agn + (size_t)r * K + lc);
                pb[u] = *(const float4*)(Wgn + (size_t)r * K + lc);
            }
        }

        const float* as = As[s];
        const float* bs = Bs[s];
#pragma unroll
        for (int ks = 0; ks < 4; ks++) {
            const int kb = ks * 8 + (lane & 3);
            uint32_t af[4][4];
#pragma unroll
            for (int i = 0; i < 4; i++) {
                int r = wm * 64 + i * 16 + (lane >> 2);
                af[i][0] = *(const uint32_t*)&as[r * TSTR + kb];
                af[i][1] = *(const uint32_t*)&as[(r + 8) * TSTR + kb];
                af[i][2] = *(const uint32_t*)&as[r * TSTR + kb + 4];
                af[i][3] = *(const uint32_t*)&as[(r + 8) * TSTR + kb + 4];
            }
            uint32_t bf[4][2];
#pragma unroll
            for (int j = 0; j < 4; j++) {
                int n = wn * 32 + j * 8 + (lane >> 2);
                bf[j][0] = *(const uint32_t*)&bs[n * TSTR + kb];
                bf[j][1] = *(const uint32_t*)&bs[n * TSTR + kb + 4];
            }
#pragma unroll
            for (int i = 0; i < 4; i++)
#pragma unroll
                for (int j = 0; j < 4; j++)
                    mma8(d[i][j], af[i], bf[j][0], bf[j][1]);
        }

        if (c + 1 < nch) {
            const int s2 = s ^ 1;
#pragma unroll
            for (int u = 0; u < 4; u++) {
                int r = lr + u * 32;
                *(float4*)(As[s2] + r * TSTR + lc) =
                    make_float4(rtf32(pa[u].x), rtf32(pa[u].y), rtf32(pa[u].z), rtf32(pa[u].w));
                *(float4*)(Bs[s2] + r * TSTR + lc) =
                    make_float4(rtf32(pb[u].x), rtf32(pb[u].y), rtf32(pb[u].z), rtf32(pb[u].w));
            }
        }
        __syncthreads();
    }

#pragma unroll
    for (int i = 0; i < 4; i++) {
        int r0 = m0 + wm * 64 + i * 16 + (lane >> 2);
#pragma unroll
        for (int j = 0; j < 4; j++) {
            int cc = n0 + wn * 32 + j * 8 + (lane & 3) * 2;
            *(float2*)(C + (size_t)r0 * N + cc)       = make_float2(d[i][j][0], d[i][j][1]);
            *(float2*)(C + (size_t)(r0 + 8) * N + cc) = make_float2(d[i][j][2], d[i][j][3]);
        }
    }
}

// ---------------------------------------------------------------------------
// Split-K reduction
// ---------------------------------------------------------------------------
__global__ __launch_bounds__(256)
void reduce_split(const float* __restrict__ part, float* __restrict__ out,
                  int n, int rnd)
{
    int i = (blockIdx.x * blockDim.x + threadIdx.x) * 4;
    if (i >= n) return;
    float4 acc = *(const float4*)(part + i);
#pragma unroll
    for (int s = 1; s < NSPLIT; s++) {
        float4 v = *(const float4*)(part + (size_t)s * n + i);
        acc.x += v.x; acc.y += v.y; acc.z += v.z; acc.w += v.w;
    }
    if (rnd) {
        acc.x = rtf32(acc.x); acc.y = rtf32(acc.y);
        acc.z = rtf32(acc.z); acc.w = rtf32(acc.w);
    }
    *(float4*)(out + i) = acc;
}

// ---------------------------------------------------------------------------
// RoPE
// ---------------------------------------------------------------------------
#define QSC (0.08838834764831845f * 1.4426950408889634f)

__global__ __launch_bounds__(256) void rope_q_kernel(
    float* __restrict__ Q, const float* __restrict__ cosp, const float* __restrict__ sinp)
{
    int i = blockIdx.x * blockDim.x + threadIdx.x;
    if (i >= NTOK * NH * 64) return;
    int d = i & 63;
    int h = (i >> 6) & 31;
    int t = i >> 11;
    int s = t & (SS - 1);
    float* q = Q + (size_t)t * HH + h * HD;
    float c1 = cosp[s * HD + d],      s1 = sinp[s * HD + d];
    float c2 = cosp[s * HD + d + 64], s2 = sinp[s * HD + d + 64];
    float x1 = q[d], x2 = q[d + 64];
    q[d]      = rtf32((x1 * c1 - x2 * s1) * QSC);
    q[d + 64] = rtf32((x2 * c2 + x1 * s2) * QSC);
}

__global__ __launch_bounds__(256) void rope_k_kernel(
    float* __restrict__ K, const float* __restrict__ cosp, const float* __restrict__ sinp)
{
    int i = blockIdx.x * blockDim.x + threadIdx.x;
    if (i >= NTOK * 64) return;
    int d = i & 63;
    int t = i >> 6;
    int s = t & (SS - 1);
    float* k = K + (size_t)t * HD;
    float c1 = cosp[s * HD + d],      s1 = sinp[s * HD + d];
    float c2 = cosp[s * HD + d + 64], s2 = sinp[s * HD + d + 64];
    float x1 = k[d], x2 = k[d + 64];
    k[d]      = rtf32(x1 * c1 - x2 * s1);
    k[d + 64] = rtf32(x2 * c2 + x1 * s2);
}

// ---------------------------------------------------------------------------
// Tensor-core flash attention (TF32 mma.sync), causal, MQA.
// O written tf32-rounded (Wd's cp.async path needs pre-rounded input).
// ---------------------------------------------------------------------------
#define ABQ 128
#define ABKV 64
#define KV_STR 136
#define P_STR 68
#define BUF_FLOATS 17408
#define P_OFF (2 * BUF_FLOATS)
#define ATT_SMEM_FLOATS (P_OFF + 128 * P_STR)
#define NEGINF (-1e30f)

__global__ __launch_bounds__(256)
void attn_mma(const float* __restrict__ Q, const float* __restrict__ Kg,
              const float* __restrict__ Vg, float* __restrict__ O)
{
    extern __shared__ float sm[];
    const int tid = threadIdx.x;
    const int lane = tid & 31, w = tid >> 5;
    const int qb = (int)gridDim.x - 1 - (int)blockIdx.x;
    const int h = blockIdx.y, b = blockIdx.z;
    const int q0 = qb * ABQ;
    const uint32_t sb = smem_u32(sm);

    {
        const float* Qg = Q + ((size_t)(b * SS + q0)) * HH + h * HD;
#pragma unroll
        for (int j = 0; j < 16; j++) {
            int i = tid + j * 256;
            int r = i >> 5, c = (i & 31) * 4;
            *(float4*)&sm[r * KV_STR + c] = *(const float4*)(Qg + (size_t)r * HH + c);
        }
    }
    __syncthreads();

    uint32_t qf[16][4];
    {
        const int r = 16 * w + (lane >> 2);
#pragma unroll
        for (int ks = 0; ks < 16; ks++) {
            int base = r * KV_STR + 8 * ks + (lane & 3);
            qf[ks][0] = *(const uint32_t*)&sm[base];
            qf[ks][1] = *(const uint32_t*)&sm[base + 8 * KV_STR];
            qf[ks][2] = *(const uint32_t*)&sm[base + 4];
            qf[ks][3] = *(const uint32_t*)&sm[base + 8 * KV_STR + 4];
        }
    }
    __syncthreads();

    float oacc[16][4];
#pragma unroll
    for (int n = 0; n < 16; n++)
#pragma unroll
        for (int q = 0; q < 4; q++) oacc[n][q] = 0.f;

    float m1 = NEGINF, m2 = NEGINF, l1 = 0.f, l2 = 0.f;

    const int ntile = (q0 + ABQ) / ABKV;
    const float* Kbase = Kg + (size_t)(b * SS) * HD;
    const float* Vbase = Vg + (size_t)(b * SS) * HD;
    const int qlo = q0 + 16 * w;
    const int qrow = qlo + (lane >> 2);

    {
#pragma unroll
        for (int j = 0; j < 8; j++) {
            int r = 8 * w + j;
            cp16(sb + (r * KV_STR + lane * 4) * 4, Kbase + (size_t)r * HD + lane * 4);
            cp16(sb + (8704 + r * KV_STR + lane * 4) * 4, Vbase + (size_t)r * HD + lane * 4);
        }
        cp_commit();
    }

    for (int t = 0; t < ntile; t++) {
        const int k0 = t * ABKV;

        if (t + 1 < ntile) {
            const int bufo = ((t + 1) & 1) * BUF_FLOATS;
            const float* Ks = Kbase + (size_t)(k0 + ABKV) * HD;
            const float* Vs = Vbase + (size_t)(k0 + ABKV) * HD;
#pragma unroll
            for (int j = 0; j < 8; j++) {
                int r = 8 * w + j;
                cp16(sb + (bufo + r * KV_STR + lane * 4) * 4, Ks + (size_t)r * HD + lane * 4);
                cp16(sb + (bufo + 8704 + r * KV_STR + lane * 4) * 4, Vs + (size_t)r * HD + lane * 4);
            }
            cp_commit();
            asm volatile("cp.async.wait_group 1;" ::: "memory");
        } else {
            asm volatile("cp.async.wait_group 0;" ::: "memory");
        }
        __syncthreads();

        if (k0 <= qlo + 15) {
            const float* Kb = sm + (t & 1) * BUF_FLOATS;
            const float* Vb = Kb + 8704;
            float* Pw = sm + P_OFF;

            float sacc[8][4];
#pragma unroll
            for (int n = 0; n < 8; n++)
#pragma unroll
                for (int q = 0; q < 4; q++) sacc[n][q] = 0.f;

#pragma unroll
            for (int ks = 0; ks < 16; ks++) {
                uint32_t bf[8][2];
#pragma unroll
                for (int nf = 0; nf < 8; nf++) {
                    int a = (8 * nf + (lane >> 2)) * KV_STR + 8 * ks + (lane & 3);
                    bf[nf][0] = *(const uint32_t*)&Kb[a];
                    bf[nf][1] = *(const uint32_t*)&Kb[a + 4];
                }
#pragma unroll
                for (int nf = 0; nf < 8; nf++)
                    mma8(sacc[nf], qf[ks], bf[nf][0], bf[nf][1]);
            }

            if (k0 + ABKV - 1 > qlo) {
#pragma unroll
                for (int nf = 0; nf < 8; nf++) {
                    int cb = k0 + 8 * nf + 2 * (lane & 3);
                    if (cb     > qrow)     sacc[nf][0] = NEGINF;
                    if (cb + 1 > qrow)     sacc[nf][1] = NEGINF;
                    if (cb     > qrow + 8) sacc[nf][2] = NEGINF;
                    if (cb + 1 > qrow + 8) sacc[nf][3] = NEGINF;
                }
            }

            float mx1 = NEGINF, mx2 = NEGINF;
#pragma unroll
            for (int nf = 0; nf < 8; nf++) {
                mx1 = fmaxf(mx1, fmaxf(sacc[nf][0], sacc[nf][1]));
                mx2 = fmaxf(mx2, fmaxf(sacc[nf][2], sacc[nf][3]));
            }
            mx1 = fmaxf(mx1, __shfl_xor_sync(0xffffffffu, mx1, 1));
            mx1 = fmaxf(mx1, __shfl_xor_sync(0xffffffffu, mx1, 2));
            mx2 = fmaxf(mx2, __shfl_xor_sync(0xffffffffu, mx2, 1));
            mx2 = fmaxf(mx2, __shfl_xor_sync(0xffffffffu, mx2, 2));
            const float mn1 = fmaxf(m1, mx1), mn2 = fmaxf(m2, mx2);
            const float a1 = ex2f(m1 - mn1), a2 = ex2f(m2 - mn2);

            float s1 = 0.f, s2 = 0.f;
            {
                const int pr = 16 * w + (lane >> 2);
                const int pcb = 2 * (lane & 3);
#pragma unroll
                for (int nf = 0; nf < 8; nf++) {
                    float p0 = ex2f(sacc[nf][0] - mn1);
                    float p1 = ex2f(sacc[nf][1] - mn1);
                    float p2 = ex2f(sacc[nf][2] - mn2);
                    float p3 = ex2f(sacc[nf][3] - mn2);
                    s1 += p0 + p1;
                    s2 += p2 + p3;
                    *(float2*)&Pw[pr * P_STR + 8 * nf + pcb] =
                        make_float2(rtf32(p0), rtf32(p1));
                    *(float2*)&Pw[(pr + 8) * P_STR + 8 * nf + pcb] =
                        make_float2(rtf32(p2), rtf32(p3));
                }
            }
            s1 += __shfl_xor_sync(0xffffffffu, s1, 1);
            s1 += __shfl_xor_sync(0xffffffffu, s1, 2);
            s2 += __shfl_xor_sync(0xffffffffu, s2, 1);
            s2 += __shfl_xor_sync(0xffffffffu, s2, 2);
            l1 = l1 * a1 + s1;
            l2 = l2 * a2 + s2;
            m1 = mn1; m2 = mn2;

#pragma unroll
            for (int n = 0; n < 16; n++) {
                oacc[n][0] *= a1; oacc[n][1] *= a1;
                oacc[n][2] *= a2; oacc[n][3] *= a2;
            }
            __syncwarp();

            const int pr = 16 * w + (lane >> 2);
#pragma unroll
            for (int kk = 0; kk < 8; kk++) {
                uint32_t pf[4];
                int pbase = pr * P_STR + 8 * kk + (lane & 3);
                pf[0] = *(const uint32_t*)&Pw[pbase];
                pf[1] = *(const uint32_t*)&Pw[pbase + 8 * P_STR];
                pf[2] = *(const uint32_t*)&Pw[pbase + 4];
                pf[3] = *(const uint32_t*)&Pw[pbase + 8 * P_STR + 4];
#pragma unroll
                for (int nf = 0; nf < 16; nf++) {
                    int a = (8 * kk + (lane & 3)) * KV_STR + 8 * nf + (lane >> 2);
                    uint32_t v0 = *(const uint32_t*)&Vb[a];
                    uint32_t v1 = *(const uint32_t*)&Vb[a + 4 * KV_STR];
                    mma8(oacc[nf], pf, v0, v1);
                }
            }
        }
        __syncthreads();
    }

    const float li1 = 1.f / l1, li2 = 1.f / l2;
    float* Ob = O + ((size_t)(b * SS + qrow)) * HH + h * HD;
#pragma unroll
    for (int nf = 0; nf < 16; nf++) {
        int col = 8 * nf + 2 * (lane & 3);
        *(float2*)(Ob + col) =
            make_float2(rtf32(oacc[nf][0] * li1), rtf32(oacc[nf][1] * li1));
        *(float2*)(Ob + (size_t)8 * HH + col) =
            make_float2(rtf32(oacc[nf][2] * li2), rtf32(oacc[nf][3] * li2));
    }
}

// ---------------------------------------------------------------------------
// kernel_launch
// ---------------------------------------------------------------------------
extern "C" void kernel_launch(void* const* d_in, const int* in_sizes, int n_in,
                              void* d_out, int out_size)
{
    const float* hs   = (const float*)d_in[0];
    const float* cosp = (const float*)d_in[1];
    const float* sinp = (const float*)d_in[2];
    const float* Wq   = (const float*)d_in[3];
    const float* Wk   = (const float*)d_in[4];
    const float* Wv   = (const float*)d_in[5];
    const float* Wd   = (const float*)d_in[6];
    float* out = (float*)d_out;

    float *pQ, *pK, *pV, *pO, *pKP, *pVP, *pHSR, *pWQR, *pWDR;
    cudaGetSymbolAddress((void**)&pQ, g_Q);
    cudaGetSymbolAddress((void**)&pK, g_K);
    cudaGetSymbolAddress((void**)&pV, g_V);
    cudaGetSymbolAddress((void**)&pO, g_O);
    cudaGetSymbolAddress((void**)&pKP, g_KP);
    cudaGetSymbolAddress((void**)&pVP, g_VP);
    cudaGetSymbolAddress((void**)&pHSR, g_HSR);
    cudaGetSymbolAddress((void**)&pWQR, g_WQR);
    cudaGetSymbolAddress((void**)&pWDR, g_WDR);

    const int gsmem = 4 * 128 * TSTR * 4;             // 73728 B
    const int asmem = ATT_SMEM_FLOATS * 4;            // 174080 B
    cudaFuncSetAttribute(gemm_big, cudaFuncAttributeMaxDynamicSharedMemorySize, BIG_SMEM);
    cudaFuncSetAttribute(gemm_mma, cudaFuncAttributeMaxDynamicSharedMemorySize, gsmem);
    cudaFuncSetAttribute(attn_mma, cudaFuncAttributeMaxDynamicSharedMemorySize, asmem);

    const int bign = NTOK * HH;   // 16.7M
    const int kvn  = NTOK * HD;   // 524288

    // Pre-round inputs for cp.async GEMMs
    round_tf32<<<bign / 4 / 256, 256>>>(hs, pHSR, bign);
    round_tf32<<<bign / 4 / 256, 256>>>(Wq, pWQR, bign);
    round_tf32<<<bign / 4 / 256, 256>>>(Wd, pWDR, bign);

    // Q projection (big tile, cp.async)
    gemm_big<<<dim3(HH / 256, NTOK / 128), 256, BIG_SMEM>>>(pHSR, pWQR, pQ);

    // K/V projections (split-K; rounds internally, rounded input is idempotent)
    gemm_mma<<<dim3(1, NTOK / 128, NSPLIT), 256, gsmem>>>(pHSR, Wk, pKP, NTOK, HD, HH, HH / NSPLIT);
    gemm_mma<<<dim3(1, NTOK / 128, NSPLIT), 256, gsmem>>>(pHSR, Wv, pVP, NTOK, HD, HH, HH / NSPLIT);
    reduce_split<<<kvn / 4 / 256, 256>>>(pKP, pK, kvn, 0);
    reduce_split<<<kvn / 4 / 256, 256>>>(pVP, pV, kvn, 1);

    // RoPE
    rope_q_kernel<<<(NTOK * NH * 64) / 256, 256>>>(pQ, cosp, sinp);
    rope_k_kernel<<<(NTOK * 64) / 256, 256>>>(pK, cosp, sinp);

    // Tensor-core flash attention (writes O tf32-rounded)
    attn_mma<<<dim3(SS / ABQ, NH, BB), 256, asmem>>>(pQ, pK, pV, pO);

    // Output projection (big tile, cp.async)
    gemm_big<<<dim3(HH / 256, NTOK / 128), 256, BIG_SMEM>>>(pO, pWDR, out);
}